// round 1
// baseline (speedup 1.0000x reference)
#include <cuda_runtime.h>
#include <cstdint>
#include <math.h>

// Problem constants
#define B_   4
#define T_   8192
#define H_   1024
#define D_   1024
#define M_   (B_*T_)     // 32768
#define CH   128         // scan chunk length
#define NC   (T_/CH)     // 64 chunks

// ---------------- scratch (device globals; no allocation allowed) -------------
__device__ float g_ih[M_*H_];     // GEMM out ih ; then cumprod P (in-place)
__device__ float g_gate[M_*H_];   // GEMM out gate-pre ; then local h (in-place)
__device__ float g_hn[M_*H_];     // layernormed h
__device__ float g_Wc[H_*D_];     // W_out @ W_proj
__device__ float g_bc[D_];        // b_out @ W_proj + b_proj
__device__ float g_cA[B_*NC*H_];  // chunk carry: prod alpha
__device__ float g_cB[B_*NC*H_];  // chunk carry: local h end
__device__ float g_cP[B_*NC*H_];  // exclusive prefix h entering each chunk

// ---------------- TF32 tensor-core GEMM --------------------------------------
#define BM 128
#define BN 128
#define BK 32
#define ASTR 36              // 36 % 32 == 4  -> conflict-free A frag loads
#define BSTR 136             // 136 % 32 == 8 -> conflict-free B frag loads
#define AS_FLOATS (BM*ASTR)  // 4608
#define BS_FLOATS (BK*BSTR)  // 4352
#define SMEM_BYTES ((2*AS_FLOATS + 2*BS_FLOATS)*4)  // 71680

__device__ __forceinline__ uint32_t f2tf(float x) {
    uint32_t r;
    asm("cvt.rna.tf32.f32 %0, %1;" : "=r"(r) : "f"(x));
    return r;
}

__device__ __forceinline__ void cp16(void* smem_dst, const void* gptr) {
    uint32_t s = (uint32_t)__cvta_generic_to_shared(smem_dst);
    asm volatile("cp.async.cg.shared.global [%0], [%1], 16;\n" :: "r"(s), "l"(gptr));
}

__device__ __forceinline__ void mma_tf32(float* d, const uint32_t* a, const uint32_t* b) {
    asm volatile(
        "mma.sync.aligned.m16n8k8.row.col.f32.tf32.tf32.f32 "
        "{%0,%1,%2,%3}, {%4,%5,%6,%7}, {%8,%9}, {%0,%1,%2,%3};\n"
        : "+f"(d[0]), "+f"(d[1]), "+f"(d[2]), "+f"(d[3])
        : "r"(a[0]), "r"(a[1]), "r"(a[2]), "r"(a[3]),
          "r"(b[0]), "r"(b[1]));
}

// C[M,N] = A[M,K] (row-major) @ B[K,N] (row-major) + bias[N]
// All dims divisible by tile sizes (M in {1024, 32768}, N = 1024, K = 1024).
__global__ void __launch_bounds__(256, 2) gemm_tf32(
    const float* __restrict__ A, const float* __restrict__ Bm,
    const float* __restrict__ bias, float* __restrict__ C,
    int Mdim, int N, int K)
{
    extern __shared__ float sm[];
    float* Asb = sm;                      // 2 stages of A: [2][BM][ASTR]
    float* Bsb = sm + 2*AS_FLOATS;        // 2 stages of B: [2][BK][BSTR]

    const int tid  = threadIdx.x;
    const int lane = tid & 31;
    const int warp = tid >> 5;
    const int g    = lane >> 2;   // 0..7
    const int tig  = lane & 3;    // 0..3
    const int wm   = warp & 1;    // 2 warps along M
    const int wn   = warp >> 1;   // 4 warps along N
    const int row0 = blockIdx.y * BM;
    const int col0 = blockIdx.x * BN;

    float acc[4][4][4];
    #pragma unroll
    for (int i = 0; i < 4; i++)
        #pragma unroll
        for (int j = 0; j < 4; j++)
            #pragma unroll
            for (int r = 0; r < 4; r++) acc[i][j][r] = 0.f;

    const int NT = K / BK;

    // ---- async tile loaders ----
    // A tile: 128x32 floats; thread t loads 4 float4: idx = t + 256*i
    //   m = idx>>3 (0..127 over passes), k4 = idx&7
    // B tile: 32x128 floats: k = idx>>5, n4 = idx&31
    auto load_tiles = [&](int st, int kt) {
        float* As = Asb + st * AS_FLOATS;
        float* Bs = Bsb + st * BS_FLOATS;
        const float* gA = A + (size_t)row0 * K + kt * BK;
        const float* gB = Bm + (size_t)(kt * BK) * N + col0;
        #pragma unroll
        for (int i = 0; i < 4; i++) {
            int idx = tid + 256 * i;
            int m = idx >> 3, k4 = idx & 7;
            cp16(As + m * ASTR + k4 * 4, gA + (size_t)m * K + k4 * 4);
        }
        #pragma unroll
        for (int i = 0; i < 4; i++) {
            int idx = tid + 256 * i;
            int k = idx >> 5, n4 = idx & 31;
            cp16(Bs + k * BSTR + n4 * 4, gB + (size_t)k * N + n4 * 4);
        }
    };

    load_tiles(0, 0);
    asm volatile("cp.async.commit_group;\n");
    asm volatile("cp.async.wait_group 0;\n");
    __syncthreads();

    for (int kt = 0; kt < NT; kt++) {
        const int st = kt & 1;
        if (kt + 1 < NT) {
            load_tiles(st ^ 1, kt + 1);
            asm volatile("cp.async.commit_group;\n");
        }

        const float* Ap = Asb + st * AS_FLOATS;
        const float* Bp = Bsb + st * BS_FLOATS;
        #pragma unroll
        for (int ks = 0; ks < 4; ks++) {
            uint32_t af[4][4], bf[4][2];
            #pragma unroll
            for (int mt = 0; mt < 4; mt++) {
                const float* p = Ap + (wm * 64 + mt * 16 + g) * ASTR + ks * 8 + tig;
                af[mt][0] = f2tf(p[0]);
                af[mt][1] = f2tf(p[8 * ASTR]);
                af[mt][2] = f2tf(p[4]);
                af[mt][3] = f2tf(p[8 * ASTR + 4]);
            }
            #pragma unroll
            for (int nt = 0; nt < 4; nt++) {
                const float* p = Bp + (ks * 8 + tig) * BSTR + wn * 32 + nt * 8 + g;
                bf[nt][0] = f2tf(p[0]);
                bf[nt][1] = f2tf(p[4 * BSTR]);
            }
            #pragma unroll
            for (int mt = 0; mt < 4; mt++)
                #pragma unroll
                for (int nt = 0; nt < 4; nt++)
                    mma_tf32(acc[mt][nt], af[mt], bf[nt]);
        }

        if (kt + 1 < NT) asm volatile("cp.async.wait_group 0;\n");
        __syncthreads();
    }

    // ---- epilogue: + bias, write float2 ----
    #pragma unroll
    for (int nt = 0; nt < 4; nt++) {
        int c = col0 + wn * 32 + nt * 8 + 2 * tig;
        float b0 = 0.f, b1 = 0.f;
        if (bias) { b0 = bias[c]; b1 = bias[c + 1]; }
        #pragma unroll
        for (int mt = 0; mt < 4; mt++) {
            int r = row0 + wm * 64 + mt * 16 + g;
            float2 v0 = make_float2(acc[mt][nt][0] + b0, acc[mt][nt][1] + b1);
            float2 v1 = make_float2(acc[mt][nt][2] + b0, acc[mt][nt][3] + b1);
            *(float2*)(C + (size_t)r * N + c)       = v0;
            *(float2*)(C + (size_t)(r + 8) * N + c) = v1;
        }
    }
}

// ---------------- scan pass 1: per-chunk local scan (in place) ----------------
// reads g_ih (pre-act ih), g_gate (pre-sigmoid gate); writes P into g_ih,
// local h into g_gate; chunk carries into g_cA/g_cB.
__global__ void __launch_bounds__(256) scan_pass1(const float* __restrict__ log_a)
{
    const int h  = blockIdx.x * 256 + threadIdx.x;
    const int ch = blockIdx.y;
    const int b  = blockIdx.z;
    const float a = expf(log_a[h]);
    int off = (b * T_ + ch * CH) * H_ + h;

    float P = 1.f, hl = 0.f;
    #pragma unroll 4
    for (int t = 0; t < CH; t++, off += H_) {
        float ihv = g_ih[off];
        float gv  = g_gate[off];
        float gt  = 1.f / (1.f + __expf(-gv));
        float alpha = (1.f - gt) * a;
        float beta  = gt * ihv;
        P *= alpha;
        hl = fmaf(alpha, hl, beta);
        g_ih[off]   = P;
        g_gate[off] = hl;
    }
    const int cidx = (b * NC + ch) * H_ + h;
    g_cA[cidx] = P;
    g_cB[cidx] = hl;
}

// ---------------- scan pass 2: scan the 64 chunk carries per channel ----------
__global__ void __launch_bounds__(256) scan_pass2()
{
    const int idx = blockIdx.x * 256 + threadIdx.x;  // over B_*H_
    const int b = idx / H_, h = idx - b * H_;
    float c = 0.f;
    #pragma unroll 4
    for (int ch = 0; ch < NC; ch++) {
        const int i = (b * NC + ch) * H_ + h;
        g_cP[i] = c;
        c = fmaf(g_cA[i], c, g_cB[i]);
    }
}

// ---------------- pass 3: carry fix-up fused with LayerNorm -------------------
__global__ void __launch_bounds__(256) fix_ln(const float* __restrict__ ln_g,
                                              const float* __restrict__ ln_b)
{
    const int row = blockIdx.x;              // b*T + t
    const int b = row / T_, t = row - b * T_;
    const int ch = t / CH;
    const int tx = threadIdx.x;

    float hv[4];
    float s = 0.f, s2 = 0.f;
    #pragma unroll
    for (int j = 0; j < 4; j++) {
        const int h   = tx + j * 256;
        const int off = row * H_ + h;
        const float c = g_cP[(b * NC + ch) * H_ + h];
        const float v = fmaf(c, g_ih[off], g_gate[off]);  // h = h_local + carry*P
        hv[j] = v;
        s += v;
        s2 = fmaf(v, v, s2);
    }

    // block reduce (s, s2)
    __shared__ float rs[8], rs2[8];
    #pragma unroll
    for (int o = 16; o > 0; o >>= 1) {
        s  += __shfl_xor_sync(0xffffffffu, s,  o);
        s2 += __shfl_xor_sync(0xffffffffu, s2, o);
    }
    const int w = tx >> 5, l = tx & 31;
    if (l == 0) { rs[w] = s; rs2[w] = s2; }
    __syncthreads();
    if (w == 0) {
        s  = (l < 8) ? rs[l]  : 0.f;
        s2 = (l < 8) ? rs2[l] : 0.f;
        #pragma unroll
        for (int o = 4; o > 0; o >>= 1) {
            s  += __shfl_xor_sync(0xffffffffu, s,  o);
            s2 += __shfl_xor_sync(0xffffffffu, s2, o);
        }
        if (l == 0) { rs[0] = s; rs2[0] = s2; }
    }
    __syncthreads();
    const float mu  = rs[0] * (1.f / H_);
    const float var = rs2[0] * (1.f / H_) - mu * mu;
    const float rstd = rsqrtf(var + 1e-5f);

    #pragma unroll
    for (int j = 0; j < 4; j++) {
        const int h   = tx + j * 256;
        const int off = row * H_ + h;
        g_hn[off] = fmaf((hv[j] - mu) * rstd, ln_g[h], ln_b[h]);
    }
}

// ---------------- combined bias: bc = b_out @ W_proj + b_proj -----------------
__global__ void __launch_bounds__(256) bias_combine(const float* __restrict__ b_out,
                                                    const float* __restrict__ W_proj,
                                                    const float* __restrict__ b_proj)
{
    const int d = blockIdx.x * 256 + threadIdx.x;
    float acc = b_proj[d];
    #pragma unroll 8
    for (int hh = 0; hh < H_; hh++)
        acc = fmaf(b_out[hh], W_proj[hh * D_ + d], acc);
    g_bc[d] = acc;
}

// ------------------------------- launch ---------------------------------------
extern "C" void kernel_launch(void* const* d_in, const int* in_sizes, int n_in,
                              void* d_out, int out_size)
{
    const float* x      = (const float*)d_in[0];
    const float* W_ih   = (const float*)d_in[1];
    const float* b_ih   = (const float*)d_in[2];
    const float* W_gate = (const float*)d_in[3];
    const float* b_gate = (const float*)d_in[4];
    const float* log_a  = (const float*)d_in[5];
    const float* ln_g   = (const float*)d_in[6];
    const float* ln_b   = (const float*)d_in[7];
    const float* W_out  = (const float*)d_in[8];
    const float* b_out  = (const float*)d_in[9];
    const float* W_proj = (const float*)d_in[10];
    const float* b_proj = (const float*)d_in[11];
    float* out = (float*)d_out;

    cudaFuncSetAttribute(gemm_tf32, cudaFuncAttributeMaxDynamicSharedMemorySize, SMEM_BYTES);

    float *p_ih, *p_gate, *p_hn, *p_Wc, *p_bc;
    cudaGetSymbolAddress((void**)&p_ih,   g_ih);
    cudaGetSymbolAddress((void**)&p_gate, g_gate);
    cudaGetSymbolAddress((void**)&p_hn,   g_hn);
    cudaGetSymbolAddress((void**)&p_Wc,   g_Wc);
    cudaGetSymbolAddress((void**)&p_bc,   g_bc);

    const dim3 blk(256);

    // W_comb = W_out @ W_proj  (folds the last two linear layers into one GEMM)
    gemm_tf32<<<dim3(D_/BN, H_/BM), blk, SMEM_BYTES>>>(W_out, W_proj, nullptr, p_Wc, H_, D_, H_);
    bias_combine<<<D_/256, blk>>>(b_out, W_proj, b_proj);

    // ih / gate pre-activations
    gemm_tf32<<<dim3(H_/BN, M_/BM), blk, SMEM_BYTES>>>(x, W_ih,   b_ih,   p_ih,   M_, H_, D_);
    gemm_tf32<<<dim3(H_/BN, M_/BM), blk, SMEM_BYTES>>>(x, W_gate, b_gate, p_gate, M_, H_, D_);

    // chunked linear recurrence + layernorm
    scan_pass1<<<dim3(H_/256, NC, B_), blk>>>(log_a);
    scan_pass2<<<(B_*H_)/256, blk>>>();
    fix_ln<<<M_, blk>>>(ln_g, ln_b);

    // out = hn @ W_comb + b_comb   (== (hn@W_out + b_out)@W_proj + b_proj)
    gemm_tf32<<<dim3(D_/BN, M_/BM), blk, SMEM_BYTES>>>(p_hn, p_Wc, p_bc, out, M_, D_, H_);
}

// round 3
// speedup vs baseline: 1.3410x; 1.3410x over previous
#include <cuda_runtime.h>
#include <cstdint>
#include <math.h>

// Problem constants
#define B_   4
#define T_   8192
#define H_   1024
#define D_   1024
#define M_   (B_*T_)     // 32768
#define CH   128
#define NC   (T_/CH)     // 64
#define NPRE 2048        // fused ih|gate width
#define BCK  16          // bias_combine split-k parts

// ---------------- scratch (device globals) ------------------------------------
__device__ float g_xr[(size_t)M_*D_];      // tf32-rounded x
__device__ float g_pre[(size_t)M_*NPRE];   // [ih | gate] pre-acts; then [P | h_local]
__device__ float g_hn[(size_t)M_*H_];      // layernormed h (tf32-rounded)
__device__ float g_Wcat[(size_t)D_*NPRE];  // [W_ih | W_gate] rounded, row-major [D,NPRE]
__device__ float g_WoutR[(size_t)H_*H_];   // W_out rounded
__device__ float g_WprojR[(size_t)H_*D_];  // W_proj rounded
__device__ float g_Wc[(size_t)H_*D_];      // W_out@W_proj rounded, row-major [H,D]
__device__ float g_b2[NPRE];               // [b_ih | b_gate]
__device__ float g_bcp[BCK*D_];            // bias_combine partials
__device__ float g_bc[D_];                 // b_out@W_proj + b_proj
__device__ float g_cA[B_*NC*H_];
__device__ float g_cB[B_*NC*H_];
__device__ float g_cP[B_*NC*H_];

// ---------------- helpers -------------------------------------------------------
__device__ __forceinline__ float f2tf_rna(float x) {
    uint32_t r; asm("cvt.rna.tf32.f32 %0, %1;" : "=r"(r) : "f"(x));
    return __uint_as_float(r);
}
__device__ __forceinline__ void cp16(void* smem_dst, const void* gptr) {
    uint32_t s = (uint32_t)__cvta_generic_to_shared(smem_dst);
    asm volatile("cp.async.cg.shared.global [%0], [%1], 16;\n" :: "r"(s), "l"(gptr));
}
__device__ __forceinline__ void mma_tf32(float* d, const uint32_t* a, const uint32_t* b) {
    asm volatile(
        "mma.sync.aligned.m16n8k8.row.col.f32.tf32.tf32.f32 "
        "{%0,%1,%2,%3}, {%4,%5,%6,%7}, {%8,%9}, {%0,%1,%2,%3};\n"
        : "+f"(d[0]), "+f"(d[1]), "+f"(d[2]), "+f"(d[3])
        : "r"(a[0]), "r"(a[1]), "r"(a[2]), "r"(a[3]),
          "r"(b[0]), "r"(b[1]));
}

// ---------------- TF32 tensor-core GEMM (inputs pre-rounded to tf32) -----------
// C[M,N] = A[M,K] (row-major) @ B[K,N] (row-major) + bias[N]
#define BM 128
#define BN 128
#define BK 32
#define ASTR 36
#define BSTR 136
#define AS_FLOATS (BM*ASTR)
#define BS_FLOATS (BK*BSTR)
#define SMEM_BYTES ((2*AS_FLOATS + 2*BS_FLOATS)*4)  // 71680

__global__ void __launch_bounds__(256, 2) gemm_tf32(
    const float* __restrict__ A, const float* __restrict__ Bm,
    const float* __restrict__ bias, float* __restrict__ C,
    int K, int N, int round_out)
{
    extern __shared__ float sm[];
    float* Asb = sm;
    float* Bsb = sm + 2*AS_FLOATS;

    const int tid  = threadIdx.x;
    const int lane = tid & 31;
    const int warp = tid >> 5;
    const int g    = lane >> 2;
    const int tig  = lane & 3;
    const int wm   = warp & 1;
    const int wn   = warp >> 1;
    const int row0 = blockIdx.y * BM;
    const int col0 = blockIdx.x * BN;

    float acc[4][4][4];
    #pragma unroll
    for (int i = 0; i < 4; i++)
        #pragma unroll
        for (int j = 0; j < 4; j++)
            #pragma unroll
            for (int r = 0; r < 4; r++) acc[i][j][r] = 0.f;

    const int NT = K / BK;

    auto load_tiles = [&](int st, int kt) {
        float* As = Asb + st * AS_FLOATS;
        float* Bs = Bsb + st * BS_FLOATS;
        const float* gA = A + (size_t)row0 * K + kt * BK;
        const float* gB = Bm + (size_t)(kt * BK) * N + col0;
        #pragma unroll
        for (int i = 0; i < 4; i++) {
            int idx = tid + 256 * i;
            int m = idx >> 3, k4 = idx & 7;
            cp16(As + m * ASTR + k4 * 4, gA + (size_t)m * K + k4 * 4);
        }
        #pragma unroll
        for (int i = 0; i < 4; i++) {
            int idx = tid + 256 * i;
            int k = idx >> 5, n4 = idx & 31;
            cp16(Bs + k * BSTR + n4 * 4, gB + (size_t)k * N + n4 * 4);
        }
    };

    load_tiles(0, 0);
    asm volatile("cp.async.commit_group;\n");
    asm volatile("cp.async.wait_group 0;\n");
    __syncthreads();

    for (int kt = 0; kt < NT; kt++) {
        const int st = kt & 1;
        if (kt + 1 < NT) {
            load_tiles(st ^ 1, kt + 1);
            asm volatile("cp.async.commit_group;\n");
        }

        const uint32_t* Ap = (const uint32_t*)(Asb + st * AS_FLOATS);
        const uint32_t* Bp = (const uint32_t*)(Bsb + st * BS_FLOATS);
        #pragma unroll
        for (int ks = 0; ks < 4; ks++) {
            uint32_t af[4][4], bf[4][2];
            #pragma unroll
            for (int mt = 0; mt < 4; mt++) {
                const uint32_t* p = Ap + (wm * 64 + mt * 16 + g) * ASTR + ks * 8 + tig;
                af[mt][0] = p[0];
                af[mt][1] = p[8 * ASTR];
                af[mt][2] = p[4];
                af[mt][3] = p[8 * ASTR + 4];
            }
            #pragma unroll
            for (int nt = 0; nt < 4; nt++) {
                const uint32_t* p = Bp + (ks * 8 + tig) * BSTR + wn * 32 + nt * 8 + g;
                bf[nt][0] = p[0];
                bf[nt][1] = p[4 * BSTR];
            }
            #pragma unroll
            for (int mt = 0; mt < 4; mt++)
                #pragma unroll
                for (int nt = 0; nt < 4; nt++)
                    mma_tf32(acc[mt][nt], af[mt], bf[nt]);
        }

        if (kt + 1 < NT) asm volatile("cp.async.wait_group 0;\n");
        __syncthreads();
    }

    #pragma unroll
    for (int nt = 0; nt < 4; nt++) {
        int c = col0 + wn * 32 + nt * 8 + 2 * tig;
        float b0 = 0.f, b1 = 0.f;
        if (bias) { b0 = bias[c]; b1 = bias[c + 1]; }
        #pragma unroll
        for (int mt = 0; mt < 4; mt++) {
            int r = row0 + wm * 64 + mt * 16 + g;
            float2 v0 = make_float2(acc[mt][nt][0] + b0, acc[mt][nt][1] + b1);
            float2 v1 = make_float2(acc[mt][nt][2] + b0, acc[mt][nt][3] + b1);
            if (round_out) {
                v0.x = f2tf_rna(v0.x); v0.y = f2tf_rna(v0.y);
                v1.x = f2tf_rna(v1.x); v1.y = f2tf_rna(v1.y);
            }
            *(float2*)(C + (size_t)r * N + c)       = v0;
            *(float2*)(C + (size_t)(r + 8) * N + c) = v1;
        }
    }
}

// ---------------- pre-passes -----------------------------------------------------
__global__ void __launch_bounds__(256) round_copy4(const float4* __restrict__ in,
                                                   float4* __restrict__ out)
{
    const size_t i = (size_t)blockIdx.x * 256 + threadIdx.x;
    float4 v = in[i];
    v.x = f2tf_rna(v.x); v.y = f2tf_rna(v.y);
    v.z = f2tf_rna(v.z); v.w = f2tf_rna(v.w);
    out[i] = v;
}

// g_Wcat[d][0:1024]=round(W_ih[d]), [1024:2048]=round(W_gate[d])
__global__ void __launch_bounds__(256) concat_round(const float4* __restrict__ Wih,
                                                    const float4* __restrict__ Wgate,
                                                    float4* __restrict__ out)
{
    const size_t i = (size_t)blockIdx.x * 256 + threadIdx.x;  // over D_*NPRE/4
    const size_t d = i >> 9;            // /512 float4 per row
    const size_t c = i & 511;
    float4 v = (c < 256) ? Wih[d * 256 + c] : Wgate[d * 256 + (c - 256)];
    v.x = f2tf_rna(v.x); v.y = f2tf_rna(v.y);
    v.z = f2tf_rna(v.z); v.w = f2tf_rna(v.w);
    out[i] = v;
}

__global__ void __launch_bounds__(256) bias_concat(const float* __restrict__ b_ih,
                                                   const float* __restrict__ b_gate)
{
    int i = blockIdx.x * 256 + threadIdx.x;
    g_b2[i]      = b_ih[i];
    g_b2[i + H_] = b_gate[i];
}

// split-k bias combine: part p sums hh in [p*64, p*64+64)
__global__ void __launch_bounds__(256) bias_comb_part(const float* __restrict__ b_out,
                                                      const float* __restrict__ W_proj)
{
    const int d = blockIdx.x * 256 + threadIdx.x;
    const int p = blockIdx.y;
    float acc = 0.f;
    #pragma unroll 8
    for (int hh = p * 64; hh < p * 64 + 64; hh++)
        acc = fmaf(b_out[hh], W_proj[(size_t)hh * D_ + d], acc);
    g_bcp[p * D_ + d] = acc;
}
__global__ void __launch_bounds__(256) bias_comb_final(const float* __restrict__ b_proj)
{
    const int d = blockIdx.x * 256 + threadIdx.x;
    float acc = b_proj[d];
    #pragma unroll
    for (int p = 0; p < BCK; p++) acc += g_bcp[p * D_ + d];
    g_bc[d] = acc;
}

// ---------------- scan pass 1 ----------------------------------------------------
__global__ void __launch_bounds__(256) scan_pass1(const float* __restrict__ log_a)
{
    const int h  = blockIdx.x * 256 + threadIdx.x;
    const int ch = blockIdx.y;
    const int b  = blockIdx.z;
    const float a = expf(log_a[h]);
    size_t off = ((size_t)(b * T_ + ch * CH)) * NPRE + h;

    float P = 1.f, hl = 0.f;
    #pragma unroll 4
    for (int t = 0; t < CH; t++, off += NPRE) {
        float ihv = g_pre[off];
        float gv  = g_pre[off + H_];
        float gt  = 1.f / (1.f + __expf(-gv));
        float alpha = (1.f - gt) * a;
        float beta  = gt * ihv;
        P *= alpha;
        hl = fmaf(alpha, hl, beta);
        g_pre[off]      = P;
        g_pre[off + H_] = hl;
    }
    const int cidx = (b * NC + ch) * H_ + h;
    g_cA[cidx] = P;
    g_cB[cidx] = hl;
}

__global__ void __launch_bounds__(256) scan_pass2()
{
    const int idx = blockIdx.x * 256 + threadIdx.x;
    const int b = idx / H_, h = idx - b * H_;
    float c = 0.f;
    #pragma unroll 4
    for (int ch = 0; ch < NC; ch++) {
        const int i = (b * NC + ch) * H_ + h;
        g_cP[i] = c;
        c = fmaf(g_cA[i], c, g_cB[i]);
    }
}

// ---------------- pass 3: carry fix-up + LayerNorm -------------------------------
__global__ void __launch_bounds__(256) fix_ln(const float* __restrict__ ln_g,
                                              const float* __restrict__ ln_b)
{
    const int row = blockIdx.x;
    const int b = row / T_, t = row - b * T_;
    const int ch = t / CH;
    const int tx = threadIdx.x;

    float hv[4];
    float s = 0.f, s2 = 0.f;
    #pragma unroll
    for (int j = 0; j < 4; j++) {
        const int h = tx + j * 256;
        const size_t off = (size_t)row * NPRE + h;
        const float c = g_cP[(b * NC + ch) * H_ + h];
        const float v = fmaf(c, g_pre[off], g_pre[off + H_]);
        hv[j] = v;
        s += v;
        s2 = fmaf(v, v, s2);
    }

    __shared__ float rs[8], rs2[8];
    #pragma unroll
    for (int o = 16; o > 0; o >>= 1) {
        s  += __shfl_xor_sync(0xffffffffu, s,  o);
        s2 += __shfl_xor_sync(0xffffffffu, s2, o);
    }
    const int w = tx >> 5, l = tx & 31;
    if (l == 0) { rs[w] = s; rs2[w] = s2; }
    __syncthreads();
    if (w == 0) {
        s  = (l < 8) ? rs[l]  : 0.f;
        s2 = (l < 8) ? rs2[l] : 0.f;
        #pragma unroll
        for (int o = 4; o > 0; o >>= 1) {
            s  += __shfl_xor_sync(0xffffffffu, s,  o);
            s2 += __shfl_xor_sync(0xffffffffu, s2, o);
        }
        if (l == 0) { rs[0] = s; rs2[0] = s2; }
    }
    __syncthreads();
    const float mu  = rs[0] * (1.f / H_);
    const float var = rs2[0] * (1.f / H_) - mu * mu;
    const float rstd = rsqrtf(var + 1e-5f);

    #pragma unroll
    for (int j = 0; j < 4; j++) {
        const int h = tx + j * 256;
        g_hn[(size_t)row * H_ + h] =
            f2tf_rna(fmaf((hv[j] - mu) * rstd, ln_g[h], ln_b[h]));
    }
}

// ------------------------------- launch -------------------------------------------
extern "C" void kernel_launch(void* const* d_in, const int* in_sizes, int n_in,
                              void* d_out, int out_size)
{
    const float* x      = (const float*)d_in[0];
    const float* W_ih   = (const float*)d_in[1];
    const float* b_ih   = (const float*)d_in[2];
    const float* W_gate = (const float*)d_in[3];
    const float* b_gate = (const float*)d_in[4];
    const float* log_a  = (const float*)d_in[5];
    const float* ln_g   = (const float*)d_in[6];
    const float* ln_b   = (const float*)d_in[7];
    const float* W_out  = (const float*)d_in[8];
    const float* b_out  = (const float*)d_in[9];
    const float* W_proj = (const float*)d_in[10];
    const float* b_proj = (const float*)d_in[11];
    float* out = (float*)d_out;

    cudaFuncSetAttribute(gemm_tf32, cudaFuncAttributeMaxDynamicSharedMemorySize, SMEM_BYTES);

    float *p_xr, *p_pre, *p_hn, *p_Wcat, *p_WoutR, *p_WprojR, *p_Wc, *p_b2, *p_bc;
    cudaGetSymbolAddress((void**)&p_xr,     g_xr);
    cudaGetSymbolAddress((void**)&p_pre,    g_pre);
    cudaGetSymbolAddress((void**)&p_hn,     g_hn);
    cudaGetSymbolAddress((void**)&p_Wcat,   g_Wcat);
    cudaGetSymbolAddress((void**)&p_WoutR,  g_WoutR);
    cudaGetSymbolAddress((void**)&p_WprojR, g_WprojR);
    cudaGetSymbolAddress((void**)&p_Wc,     g_Wc);
    cudaGetSymbolAddress((void**)&p_b2,     g_b2);
    cudaGetSymbolAddress((void**)&p_bc,     g_bc);

    const dim3 blk(256);

    // pre-round operands to tf32-exact fp32 (GEMM inner loop then loads raw bits)
    round_copy4<<<(int)((size_t)M_*D_/4/256), blk>>>((const float4*)x, (float4*)p_xr);
    concat_round<<<(int)((size_t)D_*NPRE/4/256), blk>>>((const float4*)W_ih,
                                                        (const float4*)W_gate,
                                                        (float4*)p_Wcat);
    round_copy4<<<(int)((size_t)H_*H_/4/256), blk>>>((const float4*)W_out,  (float4*)p_WoutR);
    round_copy4<<<(int)((size_t)H_*D_/4/256), blk>>>((const float4*)W_proj, (float4*)p_WprojR);
    bias_concat<<<H_/256, blk>>>(b_ih, b_gate);
    bias_comb_part<<<dim3(D_/256, BCK), blk>>>(b_out, W_proj);
    bias_comb_final<<<D_/256, blk>>>(b_proj);

    // Wc = W_out @ W_proj (rounded output)
    gemm_tf32<<<dim3(D_/BN, H_/BM), blk, SMEM_BYTES>>>(p_WoutR, p_WprojR, nullptr, p_Wc, H_, D_, 1);

    // fused [ih | gate] = x @ [W_ih | W_gate] + [b_ih | b_gate]
    gemm_tf32<<<dim3(NPRE/BN, M_/BM), blk, SMEM_BYTES>>>(p_xr, p_Wcat, p_b2, p_pre, D_, NPRE, 0);

    // chunked linear recurrence + layernorm
    scan_pass1<<<dim3(H_/256, NC, B_), blk>>>(log_a);
    scan_pass2<<<(B_*H_)/256, blk>>>();
    fix_ln<<<M_, blk>>>(ln_g, ln_b);

    // out = hn @ Wc + bc
    gemm_tf32<<<dim3(D_/BN, M_/BM), blk, SMEM_BYTES>>>(p_hn, p_Wc, p_bc, out, H_, D_, 0);
}

// round 4
// speedup vs baseline: 2.2053x; 1.6445x over previous
#include <cuda_runtime.h>
#include <cuda_fp16.h>
#include <cstdint>
#include <math.h>

// Problem constants
#define B_   4
#define T_   8192
#define H_   1024
#define D_   1024
#define M_   (B_*T_)     // 32768
#define CH   128
#define NC   (T_/CH)     // 64
#define NPRE 2048
#define BCK  16

// ---------------- scratch (device globals) ------------------------------------
__device__ __half g_xh[(size_t)M_*D_];       // fp16 x
__device__ float  g_pre[(size_t)M_*NPRE];    // [ih | gate] pre-acts; then [P | h_local]
__device__ __half g_hn[(size_t)M_*H_];       // layernormed h (fp16)
__device__ __half g_WcatT[(size_t)NPRE*D_];  // [W_ih^T ; W_gate^T] fp16, [2048][1024]
__device__ __half g_WoutH[(size_t)H_*H_];    // W_out fp16 row-major
__device__ __half g_WprojT[(size_t)D_*H_];   // W_proj^T fp16 [D][H]
__device__ float  g_Wc[(size_t)H_*D_];       // W_out@W_proj fp32 [H][D]
__device__ __half g_WcT[(size_t)D_*H_];      // Wc^T fp16 [D][H]
__device__ float  g_b2[NPRE];
__device__ float  g_bcp[BCK*D_];
__device__ float  g_bc[D_];
__device__ float  g_cA[B_*NC*H_];
__device__ float  g_cB[B_*NC*H_];
__device__ float  g_cP[B_*NC*H_];

// ---------------- helpers -------------------------------------------------------
__device__ __forceinline__ void cp16(void* smem_dst, const void* gptr) {
    uint32_t s = (uint32_t)__cvta_generic_to_shared(smem_dst);
    asm volatile("cp.async.cg.shared.global [%0], [%1], 16;\n" :: "r"(s), "l"(gptr));
}
__device__ __forceinline__ void mma_f16(float* d, const uint32_t* a, const uint32_t* b) {
    asm volatile(
        "mma.sync.aligned.m16n8k16.row.col.f32.f16.f16.f32 "
        "{%0,%1,%2,%3}, {%4,%5,%6,%7}, {%8,%9}, {%0,%1,%2,%3};\n"
        : "+f"(d[0]), "+f"(d[1]), "+f"(d[2]), "+f"(d[3])
        : "r"(a[0]), "r"(a[1]), "r"(a[2]), "r"(a[3]),
          "r"(b[0]), "r"(b[1]));
}

// ---------------- FP16 tensor-core GEMM -----------------------------------------
// C[M,N] = A[M,K](fp16 row-major) @ Bt[N,K](fp16 row-major)^T + bias[N], fp32 out
#define BM 128
#define BN 128
#define BK 64
#define ASTR 72                       // halfs per smem row (stride 36 words == 4 mod 32)
#define AS_HALFS (BM*ASTR)            // 9216
#define BS_HALFS (BN*ASTR)            // 9216
#define SMEM_BYTES (2*(AS_HALFS+BS_HALFS)*2)  // 73728

__global__ void __launch_bounds__(256, 2) gemm_f16(
    const __half* __restrict__ A, const __half* __restrict__ Bt,
    const float* __restrict__ bias, float* __restrict__ C,
    int K, int N)
{
    extern __shared__ __half smh[];
    __half* Asb = smh;
    __half* Bsb = smh + 2*AS_HALFS;

    const int tid  = threadIdx.x;
    const int lane = tid & 31;
    const int warp = tid >> 5;
    const int g    = lane >> 2;   // 0..7
    const int tig  = lane & 3;    // 0..3
    const int wm   = warp & 1;
    const int wn   = warp >> 1;
    const int row0 = blockIdx.y * BM;
    const int col0 = blockIdx.x * BN;

    float acc[4][4][4];
    #pragma unroll
    for (int i = 0; i < 4; i++)
        #pragma unroll
        for (int j = 0; j < 4; j++)
            #pragma unroll
            for (int r = 0; r < 4; r++) acc[i][j][r] = 0.f;

    const int NT = K / BK;

    // tiles: 128 rows x 64 halfs (128B) each for A and B -> 8 chunks/row
    auto load_tiles = [&](int st, int kt) {
        __half* As = Asb + st * AS_HALFS;
        __half* Bs = Bsb + st * BS_HALFS;
        const __half* gA = A  + (size_t)row0 * K + kt * BK;
        const __half* gB = Bt + (size_t)col0 * K + kt * BK;
        #pragma unroll
        for (int i = 0; i < 4; i++) {
            int idx = tid + 256 * i;
            int r = idx >> 3, c = idx & 7;
            cp16(As + r * ASTR + c * 8, gA + (size_t)r * K + c * 8);
        }
        #pragma unroll
        for (int i = 0; i < 4; i++) {
            int idx = tid + 256 * i;
            int r = idx >> 3, c = idx & 7;
            cp16(Bs + r * ASTR + c * 8, gB + (size_t)r * K + c * 8);
        }
    };

    load_tiles(0, 0);
    asm volatile("cp.async.commit_group;\n");
    asm volatile("cp.async.wait_group 0;\n");
    __syncthreads();

    for (int kt = 0; kt < NT; kt++) {
        const int st = kt & 1;
        if (kt + 1 < NT) {
            load_tiles(st ^ 1, kt + 1);
            asm volatile("cp.async.commit_group;\n");
        }

        const uint32_t* Ap = (const uint32_t*)(Asb + st * AS_HALFS);
        const uint32_t* Bp = (const uint32_t*)(Bsb + st * BS_HALFS);
        #pragma unroll
        for (int ks = 0; ks < 4; ks++) {          // 4 x k16
            uint32_t af[4][4], bf[4][2];
            #pragma unroll
            for (int mt = 0; mt < 4; mt++) {
                const int base = (wm * 64 + mt * 16 + g) * 36 + ks * 8 + tig;
                af[mt][0] = Ap[base];
                af[mt][1] = Ap[base + 8 * 36];
                af[mt][2] = Ap[base + 4];
                af[mt][3] = Ap[base + 8 * 36 + 4];
            }
            #pragma unroll
            for (int nt = 0; nt < 4; nt++) {
                const int base = (wn * 32 + nt * 8 + g) * 36 + ks * 8 + tig;
                bf[nt][0] = Bp[base];
                bf[nt][1] = Bp[base + 4];
            }
            #pragma unroll
            for (int mt = 0; mt < 4; mt++)
                #pragma unroll
                for (int nt = 0; nt < 4; nt++)
                    mma_f16(acc[mt][nt], af[mt], bf[nt]);
        }

        if (kt + 1 < NT) asm volatile("cp.async.wait_group 0;\n");
        __syncthreads();
    }

    #pragma unroll
    for (int nt = 0; nt < 4; nt++) {
        int c = col0 + wn * 32 + nt * 8 + 2 * tig;
        float b0 = 0.f, b1 = 0.f;
        if (bias) { b0 = bias[c]; b1 = bias[c + 1]; }
        #pragma unroll
        for (int mt = 0; mt < 4; mt++) {
            int r = row0 + wm * 64 + mt * 16 + g;
            float2 v0 = make_float2(acc[mt][nt][0] + b0, acc[mt][nt][1] + b1);
            float2 v1 = make_float2(acc[mt][nt][2] + b0, acc[mt][nt][3] + b1);
            *(float2*)(C + (size_t)r * N + c)       = v0;
            *(float2*)(C + (size_t)(r + 8) * N + c) = v1;
        }
    }
}

// ---------------- pre-passes -----------------------------------------------------
// fp32 -> fp16 row-major copy; 8 floats -> one 16B store per thread
__global__ void __launch_bounds__(256) conv_h8(const float4* __restrict__ in,
                                               uint4* __restrict__ out)
{
    const size_t i = (size_t)blockIdx.x * 256 + threadIdx.x;
    float4 v0 = in[2 * i], v1 = in[2 * i + 1];
    __half2 h0 = __floats2half2_rn(v0.x, v0.y);
    __half2 h1 = __floats2half2_rn(v0.z, v0.w);
    __half2 h2 = __floats2half2_rn(v1.x, v1.y);
    __half2 h3 = __floats2half2_rn(v1.z, v1.w);
    uint4 o;
    o.x = *(uint32_t*)&h0; o.y = *(uint32_t*)&h1;
    o.z = *(uint32_t*)&h2; o.w = *(uint32_t*)&h3;
    out[i] = o;
}

// out[C][R] = fp16(in[R][C]^T). block (32,8), grid (C/32, R/32)
__global__ void __launch_bounds__(256) trans_h(const float* __restrict__ in,
                                               __half* __restrict__ out,
                                               int R, int C)
{
    __shared__ float t[32][33];
    int bx = blockIdx.x * 32, by = blockIdx.y * 32;
    #pragma unroll
    for (int j = 0; j < 32; j += 8)
        t[threadIdx.y + j][threadIdx.x] =
            in[(size_t)(by + threadIdx.y + j) * C + bx + threadIdx.x];
    __syncthreads();
    #pragma unroll
    for (int j = 0; j < 32; j += 8)
        out[(size_t)(bx + threadIdx.y + j) * R + by + threadIdx.x] =
            __float2half_rn(t[threadIdx.x][threadIdx.y + j]);
}

__global__ void __launch_bounds__(256) bias_concat(const float* __restrict__ b_ih,
                                                   const float* __restrict__ b_gate)
{
    int i = blockIdx.x * 256 + threadIdx.x;
    g_b2[i]      = b_ih[i];
    g_b2[i + H_] = b_gate[i];
}

__global__ void __launch_bounds__(256) bias_comb_part(const float* __restrict__ b_out,
                                                      const float* __restrict__ W_proj)
{
    const int d = blockIdx.x * 256 + threadIdx.x;
    const int p = blockIdx.y;
    float acc = 0.f;
    #pragma unroll 8
    for (int hh = p * 64; hh < p * 64 + 64; hh++)
        acc = fmaf(b_out[hh], W_proj[(size_t)hh * D_ + d], acc);
    g_bcp[p * D_ + d] = acc;
}
__global__ void __launch_bounds__(256) bias_comb_final(const float* __restrict__ b_proj)
{
    const int d = blockIdx.x * 256 + threadIdx.x;
    float acc = b_proj[d];
    #pragma unroll
    for (int p = 0; p < BCK; p++) acc += g_bcp[p * D_ + d];
    g_bc[d] = acc;
}

// ---------------- scan pass 1 ----------------------------------------------------
__global__ void __launch_bounds__(256) scan_pass1(const float* __restrict__ log_a)
{
    const int h  = blockIdx.x * 256 + threadIdx.x;
    const int ch = blockIdx.y;
    const int b  = blockIdx.z;
    const float a = expf(log_a[h]);
    size_t off = ((size_t)(b * T_ + ch * CH)) * NPRE + h;

    float P = 1.f, hl = 0.f;
    #pragma unroll 4
    for (int t = 0; t < CH; t++, off += NPRE) {
        float ihv = g_pre[off];
        float gv  = g_pre[off + H_];
        float gt  = 1.f / (1.f + __expf(-gv));
        float alpha = (1.f - gt) * a;
        float beta  = gt * ihv;
        P *= alpha;
        hl = fmaf(alpha, hl, beta);
        g_pre[off]      = P;
        g_pre[off + H_] = hl;
    }
    const int cidx = (b * NC + ch) * H_ + h;
    g_cA[cidx] = P;
    g_cB[cidx] = hl;
}

__global__ void __launch_bounds__(256) scan_pass2()
{
    const int idx = blockIdx.x * 256 + threadIdx.x;
    const int b = idx / H_, h = idx - b * H_;
    float c = 0.f;
    #pragma unroll 4
    for (int ch = 0; ch < NC; ch++) {
        const int i = (b * NC + ch) * H_ + h;
        g_cP[i] = c;
        c = fmaf(g_cA[i], c, g_cB[i]);
    }
}

// ---------------- pass 3: carry fix-up + LayerNorm (fp16 out) --------------------
__global__ void __launch_bounds__(256) fix_ln(const float* __restrict__ ln_g,
                                              const float* __restrict__ ln_b)
{
    const int row = blockIdx.x;
    const int b = row / T_, t = row - b * T_;
    const int ch = t / CH;
    const int tx = threadIdx.x;

    float hv[4];
    float s = 0.f, s2 = 0.f;
    #pragma unroll
    for (int j = 0; j < 4; j++) {
        const int h = tx + j * 256;
        const size_t off = (size_t)row * NPRE + h;
        const float c = g_cP[(b * NC + ch) * H_ + h];
        const float v = fmaf(c, g_pre[off], g_pre[off + H_]);
        hv[j] = v;
        s += v;
        s2 = fmaf(v, v, s2);
    }

    __shared__ float rs[8], rs2[8];
    #pragma unroll
    for (int o = 16; o > 0; o >>= 1) {
        s  += __shfl_xor_sync(0xffffffffu, s,  o);
        s2 += __shfl_xor_sync(0xffffffffu, s2, o);
    }
    const int w = tx >> 5, l = tx & 31;
    if (l == 0) { rs[w] = s; rs2[w] = s2; }
    __syncthreads();
    if (w == 0) {
        s  = (l < 8) ? rs[l]  : 0.f;
        s2 = (l < 8) ? rs2[l] : 0.f;
        #pragma unroll
        for (int o = 4; o > 0; o >>= 1) {
            s  += __shfl_xor_sync(0xffffffffu, s,  o);
            s2 += __shfl_xor_sync(0xffffffffu, s2, o);
        }
        if (l == 0) { rs[0] = s; rs2[0] = s2; }
    }
    __syncthreads();
    const float mu  = rs[0] * (1.f / H_);
    const float var = rs2[0] * (1.f / H_) - mu * mu;
    const float rstd = rsqrtf(var + 1e-5f);

    #pragma unroll
    for (int j = 0; j < 4; j++) {
        const int h = tx + j * 256;
        g_hn[(size_t)row * H_ + h] =
            __float2half_rn(fmaf((hv[j] - mu) * rstd, ln_g[h], ln_b[h]));
    }
}

// ------------------------------- launch -------------------------------------------
extern "C" void kernel_launch(void* const* d_in, const int* in_sizes, int n_in,
                              void* d_out, int out_size)
{
    const float* x      = (const float*)d_in[0];
    const float* W_ih   = (const float*)d_in[1];
    const float* b_ih   = (const float*)d_in[2];
    const float* W_gate = (const float*)d_in[3];
    const float* b_gate = (const float*)d_in[4];
    const float* log_a  = (const float*)d_in[5];
    const float* ln_g   = (const float*)d_in[6];
    const float* ln_b   = (const float*)d_in[7];
    const float* W_out  = (const float*)d_in[8];
    const float* b_out  = (const float*)d_in[9];
    const float* W_proj = (const float*)d_in[10];
    const float* b_proj = (const float*)d_in[11];
    float* out = (float*)d_out;

    cudaFuncSetAttribute(gemm_f16, cudaFuncAttributeMaxDynamicSharedMemorySize, SMEM_BYTES);

    __half *p_xh, *p_hn, *p_WcatT, *p_WoutH, *p_WprojT, *p_WcT;
    float *p_pre, *p_Wc, *p_b2, *p_bc;
    cudaGetSymbolAddress((void**)&p_xh,     g_xh);
    cudaGetSymbolAddress((void**)&p_pre,    g_pre);
    cudaGetSymbolAddress((void**)&p_hn,     g_hn);
    cudaGetSymbolAddress((void**)&p_WcatT,  g_WcatT);
    cudaGetSymbolAddress((void**)&p_WoutH,  g_WoutH);
    cudaGetSymbolAddress((void**)&p_WprojT, g_WprojT);
    cudaGetSymbolAddress((void**)&p_Wc,     g_Wc);
    cudaGetSymbolAddress((void**)&p_WcT,    g_WcT);
    cudaGetSymbolAddress((void**)&p_b2,     g_b2);
    cudaGetSymbolAddress((void**)&p_bc,     g_bc);

    const dim3 blk(256);
    const dim3 tblk(32, 8);
    const dim3 tg(32, 32);

    // convert / transpose operands to fp16
    conv_h8<<<(int)((size_t)M_*D_/8/256), blk>>>((const float4*)x, (uint4*)p_xh);
    trans_h<<<tg, tblk>>>(W_ih,   p_WcatT,                    D_, H_);  // [H][D]
    trans_h<<<tg, tblk>>>(W_gate, p_WcatT + (size_t)H_*D_,    D_, H_);
    trans_h<<<tg, tblk>>>(W_proj, p_WprojT,                   H_, D_);  // [D][H]
    conv_h8<<<(int)((size_t)H_*H_/8/256), blk>>>((const float4*)W_out, (uint4*)p_WoutH);
    bias_concat<<<H_/256, blk>>>(b_ih, b_gate);
    bias_comb_part<<<dim3(D_/256, BCK), blk>>>(b_out, W_proj);
    bias_comb_final<<<D_/256, blk>>>(b_proj);

    // Wc = W_out @ W_proj (fp32 out), then transpose to fp16 [D][H]
    gemm_f16<<<dim3(D_/BN, H_/BM), blk, SMEM_BYTES>>>(p_WoutH, p_WprojT, nullptr, p_Wc, H_, D_);
    trans_h<<<tg, tblk>>>(p_Wc, p_WcT, H_, D_);

    // fused [ih | gate] = x @ [W_ih | W_gate] + [b_ih | b_gate]
    gemm_f16<<<dim3(NPRE/BN, M_/BM), blk, SMEM_BYTES>>>(p_xh, p_WcatT, p_b2, p_pre, D_, NPRE);

    // chunked linear recurrence + layernorm
    scan_pass1<<<dim3(H_/256, NC, B_), blk>>>(log_a);
    scan_pass2<<<(B_*H_)/256, blk>>>();
    fix_ln<<<M_, blk>>>(ln_g, ln_b);

    // out = hn @ Wc + bc
    gemm_f16<<<dim3(D_/BN, M_/BM), blk, SMEM_BYTES>>>(p_hn, p_WcT, p_bc, out, H_, D_);
}

// round 5
// speedup vs baseline: 2.4937x; 1.1308x over previous
#include <cuda_runtime.h>
#include <cuda_fp16.h>
#include <cstdint>
#include <math.h>

// Problem constants
#define B_   4
#define T_   8192
#define H_   1024
#define D_   1024
#define M_   (B_*T_)     // 32768
#define CH   128
#define NC   (T_/CH)     // 64
#define NPRE 2048
#define BCK  16

// ---------------- scratch (device globals) ------------------------------------
__device__ __half g_xh[(size_t)M_*D_];       // fp16 x
__device__ float  g_pre[(size_t)M_*NPRE];    // interleaved (P, h_local) float2 per channel
__device__ __half g_hn[(size_t)M_*H_];       // layernormed h (fp16)
__device__ __half g_WcatT[(size_t)NPRE*D_];  // interleaved [2048][1024]: row 2h=W_ih^T_h, 2h+1=W_gate^T_h
__device__ __half g_WoutH[(size_t)H_*H_];    // W_out fp16 row-major
__device__ __half g_WprojT[(size_t)D_*H_];   // W_proj^T fp16 [D][H]
__device__ float  g_Wc[(size_t)H_*D_];       // W_out@W_proj fp32 [H][D]
__device__ __half g_WcT[(size_t)D_*H_];      // Wc^T fp16 [D][H]
__device__ float  g_b2[NPRE];                // interleaved [b_ih_h, b_gate_h]
__device__ float  g_bcp[BCK*D_];
__device__ float  g_bc[D_];
__device__ float  g_cA[B_*NC*H_];
__device__ float  g_cB[B_*NC*H_];
__device__ float  g_cP[B_*NC*H_];

// ---------------- helpers -------------------------------------------------------
__device__ __forceinline__ void cp16(void* smem_dst, const void* gptr) {
    uint32_t s = (uint32_t)__cvta_generic_to_shared(smem_dst);
    asm volatile("cp.async.cg.shared.global [%0], [%1], 16;\n" :: "r"(s), "l"(gptr));
}
__device__ __forceinline__ void mma_f16(float* d, const uint32_t* a, uint32_t b0, uint32_t b1) {
    asm volatile(
        "mma.sync.aligned.m16n8k16.row.col.f32.f16.f16.f32 "
        "{%0,%1,%2,%3}, {%4,%5,%6,%7}, {%8,%9}, {%0,%1,%2,%3};\n"
        : "+f"(d[0]), "+f"(d[1]), "+f"(d[2]), "+f"(d[3])
        : "r"(a[0]), "r"(a[1]), "r"(a[2]), "r"(a[3]), "r"(b0), "r"(b1));
}
#define LDSM4(r, addr)                                                            \
    asm volatile("ldmatrix.sync.aligned.m8n8.x4.shared.b16 {%0,%1,%2,%3}, [%4];"  \
        : "=r"((r)[0]), "=r"((r)[1]), "=r"((r)[2]), "=r"((r)[3]) : "r"(addr))

// ---------------- FP16 tensor-core GEMM -----------------------------------------
// C[M,N] = A[M,K](fp16 rm) @ Bt[N,K](fp16 rm)^T + bias[N]
// mode 0: plain fp32 store.  mode 1: fused chunk-scan epilogue (pre-GEMM only).
#define BM 128
#define BN 128
#define BK 64
#define ASTR 72                        // halfs per smem row (144B)
#define AS_HALFS (BM*ASTR)
#define BS_HALFS (BN*ASTR)
#define SMEM_BYTES (2*(AS_HALFS+BS_HALFS)*2)  // 73728
#define SSTR 68                        // scan smem stride (floats)

__global__ void __launch_bounds__(256, 2) gemm_f16(
    const __half* __restrict__ A, const __half* __restrict__ Bt,
    const float* __restrict__ bias, float* __restrict__ C,
    int K, int N, int mode, const float* __restrict__ log_a)
{
    extern __shared__ __half smh[];
    __half* Asb = smh;
    __half* Bsb = smh + 2*AS_HALFS;

    const int tid  = threadIdx.x;
    const int lane = tid & 31;
    const int warp = tid >> 5;
    const int g    = lane >> 2;
    const int tig  = lane & 3;
    const int wm   = warp & 1;
    const int wn   = warp >> 1;
    const int row0 = blockIdx.y * BM;
    const int col0 = blockIdx.x * BN;

    float acc[4][4][4];
    #pragma unroll
    for (int i = 0; i < 4; i++)
        #pragma unroll
        for (int j = 0; j < 4; j++)
            #pragma unroll
            for (int r = 0; r < 4; r++) acc[i][j][r] = 0.f;

    const int NT = K / BK;

    // ldmatrix per-lane byte offsets (within a stage)
    const uint32_t As0 = (uint32_t)__cvta_generic_to_shared(Asb);
    const uint32_t Bs0 = (uint32_t)__cvta_generic_to_shared(Bsb);
    const uint32_t aoff = ((wm * 64 + (lane & 15)) * ASTR + (lane >> 4) * 8) * 2;
    const uint32_t boff = ((wn * 32 + (lane & 7) + (lane >> 4) * 8) * ASTR
                           + ((lane >> 3) & 1) * 8) * 2;

    auto load_tiles = [&](int st, int kt) {
        __half* As = Asb + st * AS_HALFS;
        __half* Bs = Bsb + st * BS_HALFS;
        const __half* gA = A  + (size_t)row0 * K + kt * BK;
        const __half* gB = Bt + (size_t)col0 * K + kt * BK;
        #pragma unroll
        for (int i = 0; i < 4; i++) {
            int idx = tid + 256 * i;
            int r = idx >> 3, c = idx & 7;
            cp16(As + r * ASTR + c * 8, gA + (size_t)r * K + c * 8);
        }
        #pragma unroll
        for (int i = 0; i < 4; i++) {
            int idx = tid + 256 * i;
            int r = idx >> 3, c = idx & 7;
            cp16(Bs + r * ASTR + c * 8, gB + (size_t)r * K + c * 8);
        }
    };

    load_tiles(0, 0);
    asm volatile("cp.async.commit_group;\n");
    asm volatile("cp.async.wait_group 0;\n");
    __syncthreads();

    for (int kt = 0; kt < NT; kt++) {
        const int st = kt & 1;
        if (kt + 1 < NT) {
            load_tiles(st ^ 1, kt + 1);
            asm volatile("cp.async.commit_group;\n");
        }

        const uint32_t aBase = As0 + st * (AS_HALFS * 2) + aoff;
        const uint32_t bBase = Bs0 + st * (BS_HALFS * 2) + boff;
        #pragma unroll
        for (int ks = 0; ks < 4; ks++) {
            uint32_t af[4][4], bf[2][4];
            #pragma unroll
            for (int mt = 0; mt < 4; mt++)
                LDSM4(af[mt], aBase + (mt * 16 * ASTR + ks * 16) * 2);
            #pragma unroll
            for (int ntp = 0; ntp < 2; ntp++)
                LDSM4(bf[ntp], bBase + (ntp * 16 * ASTR + ks * 16) * 2);
            #pragma unroll
            for (int mt = 0; mt < 4; mt++)
                #pragma unroll
                for (int nt = 0; nt < 4; nt++)
                    mma_f16(acc[mt][nt], af[mt],
                            bf[nt >> 1][(nt & 1) * 2], bf[nt >> 1][(nt & 1) * 2 + 1]);
        }

        if (kt + 1 < NT) asm volatile("cp.async.wait_group 0;\n");
        __syncthreads();
    }

    if (mode == 0) {
        #pragma unroll
        for (int nt = 0; nt < 4; nt++) {
            int c = col0 + wn * 32 + nt * 8 + 2 * tig;
            float b0 = 0.f, b1 = 0.f;
            if (bias) { b0 = bias[c]; b1 = bias[c + 1]; }
            #pragma unroll
            for (int mt = 0; mt < 4; mt++) {
                int r = row0 + wm * 64 + mt * 16 + g;
                float2 v0 = make_float2(acc[mt][nt][0] + b0, acc[mt][nt][1] + b1);
                float2 v1 = make_float2(acc[mt][nt][2] + b0, acc[mt][nt][3] + b1);
                *(float2*)(C + (size_t)r * N + c)       = v0;
                *(float2*)(C + (size_t)(r + 8) * N + c) = v1;
            }
        }
        return;
    }

    // ---- mode 1: fused chunk-local scan epilogue ----
    // Each accumulator col pair (c,c+1) = (ih, gate) of channel hloc = c/2.
    float* sA = (float*)smh;            // alpha [128][SSTR]
    float* sB = sA + 128 * SSTR;        // beta

    #pragma unroll
    for (int nt = 0; nt < 4; nt++) {
        const int c    = wn * 32 + nt * 8 + 2 * tig;       // local, even
        const int hloc = c >> 1;
        const int hg   = (col0 >> 1) + hloc;
        const float bi = bias[col0 + c];
        const float bg = bias[col0 + c + 1];
        const float av = expf(log_a[hg]);
        #pragma unroll
        for (int mt = 0; mt < 4; mt++) {
            const int r = wm * 64 + mt * 16 + g;
            {
                float ih = acc[mt][nt][0] + bi;
                float gp = acc[mt][nt][1] + bg;
                float gt = 1.f / (1.f + __expf(-gp));
                sA[r * SSTR + hloc] = (1.f - gt) * av;
                sB[r * SSTR + hloc] = gt * ih;
            }
            {
                float ih = acc[mt][nt][2] + bi;
                float gp = acc[mt][nt][3] + bg;
                float gt = 1.f / (1.f + __expf(-gp));
                sA[(r + 8) * SSTR + hloc] = (1.f - gt) * av;
                sB[(r + 8) * SSTR + hloc] = gt * ih;
            }
        }
    }
    __syncthreads();

    // serial scan over two halves of 64 steps (in place)
    if (tid < 128) {
        const int h = tid & 63, half = tid >> 6;
        float P = 1.f, hl = 0.f;
        int base = (half * 64) * SSTR + h;
        #pragma unroll 8
        for (int i = 0; i < 64; i++, base += SSTR) {
            float al = sA[base], be = sB[base];
            P *= al;
            hl = fmaf(al, hl, be);
            sA[base] = P;
            sB[base] = hl;
        }
    }
    __syncthreads();

    // fix-up second half + store (P, h_local) interleaved; emit carries at t=127
    const int bb  = row0 / T_;
    const int chh = (row0 - bb * T_) >> 7;
    #pragma unroll
    for (int k = 0; k < 32; k++) {
        const int e = tid + 256 * k;          // 128*64 elements
        const int t = e >> 6, h = e & 63;
        float P  = sA[t * SSTR + h];
        float hl = sB[t * SSTR + h];
        if (t >= 64) {
            const float Pm = sA[63 * SSTR + h];
            const float hm = sB[63 * SSTR + h];
            hl = fmaf(P, hm, hl);
            P  = P * Pm;
        }
        const int hg = (col0 >> 1) + h;
        *(float2*)(C + (size_t)(row0 + t) * N + 2 * hg) = make_float2(P, hl);
        if (t == 127) {
            const int ci = (bb * NC + chh) * H_ + hg;
            g_cA[ci] = P;
            g_cB[ci] = hl;
        }
    }
}

// ---------------- pre-passes -----------------------------------------------------
__global__ void __launch_bounds__(256) conv_h8(const float4* __restrict__ in,
                                               uint4* __restrict__ out)
{
    const size_t i = (size_t)blockIdx.x * 256 + threadIdx.x;
    float4 v0 = in[2 * i], v1 = in[2 * i + 1];
    __half2 h0 = __floats2half2_rn(v0.x, v0.y);
    __half2 h1 = __floats2half2_rn(v0.z, v0.w);
    __half2 h2 = __floats2half2_rn(v1.x, v1.y);
    __half2 h3 = __floats2half2_rn(v1.z, v1.w);
    uint4 o;
    o.x = *(uint32_t*)&h0; o.y = *(uint32_t*)&h1;
    o.z = *(uint32_t*)&h2; o.w = *(uint32_t*)&h3;
    out[i] = o;
}

// out[C][R] = fp16(in[R][C]^T)
__global__ void __launch_bounds__(256) trans_h(const float* __restrict__ in,
                                               __half* __restrict__ out,
                                               int R, int C)
{
    __shared__ float t[32][33];
    int bx = blockIdx.x * 32, by = blockIdx.y * 32;
    #pragma unroll
    for (int j = 0; j < 32; j += 8)
        t[threadIdx.y + j][threadIdx.x] =
            in[(size_t)(by + threadIdx.y + j) * C + bx + threadIdx.x];
    __syncthreads();
    #pragma unroll
    for (int j = 0; j < 32; j += 8)
        out[(size_t)(bx + threadIdx.y + j) * R + by + threadIdx.x] =
            __float2half_rn(t[threadIdx.x][threadIdx.y + j]);
}

// interleaved transpose: out[2*col + sel][row] = fp16(in[row][col]); in [R][C]
__global__ void __launch_bounds__(256) trans_h_il(const float* __restrict__ in,
                                                  __half* __restrict__ out,
                                                  int R, int C, int sel)
{
    __shared__ float t[32][33];
    int bx = blockIdx.x * 32, by = blockIdx.y * 32;
    #pragma unroll
    for (int j = 0; j < 32; j += 8)
        t[threadIdx.y + j][threadIdx.x] =
            in[(size_t)(by + threadIdx.y + j) * C + bx + threadIdx.x];
    __syncthreads();
    #pragma unroll
    for (int j = 0; j < 32; j += 8)
        out[(size_t)(2 * (bx + threadIdx.y + j) + sel) * R + by + threadIdx.x] =
            __float2half_rn(t[threadIdx.x][threadIdx.y + j]);
}

__global__ void __launch_bounds__(256) bias_concat(const float* __restrict__ b_ih,
                                                   const float* __restrict__ b_gate)
{
    int i = blockIdx.x * 256 + threadIdx.x;
    g_b2[2 * i]     = b_ih[i];
    g_b2[2 * i + 1] = b_gate[i];
}

__global__ void __launch_bounds__(256) bias_comb_part(const float* __restrict__ b_out,
                                                      const float* __restrict__ W_proj)
{
    const int d = blockIdx.x * 256 + threadIdx.x;
    const int p = blockIdx.y;
    float acc = 0.f;
    #pragma unroll 8
    for (int hh = p * 64; hh < p * 64 + 64; hh++)
        acc = fmaf(b_out[hh], W_proj[(size_t)hh * D_ + d], acc);
    g_bcp[p * D_ + d] = acc;
}
__global__ void __launch_bounds__(256) bias_comb_final(const float* __restrict__ b_proj)
{
    const int d = blockIdx.x * 256 + threadIdx.x;
    float acc = b_proj[d];
    #pragma unroll
    for (int p = 0; p < BCK; p++) acc += g_bcp[p * D_ + d];
    g_bc[d] = acc;
}

// ---------------- scan pass 2: scan chunk carries --------------------------------
__global__ void __launch_bounds__(256) scan_pass2()
{
    const int idx = blockIdx.x * 256 + threadIdx.x;
    const int b = idx / H_, h = idx - b * H_;
    float c = 0.f;
    #pragma unroll 4
    for (int ch = 0; ch < NC; ch++) {
        const int i = (b * NC + ch) * H_ + h;
        g_cP[i] = c;
        c = fmaf(g_cA[i], c, g_cB[i]);
    }
}

// ---------------- pass 3: carry fix-up + LayerNorm (fp16 out) --------------------
__global__ void __launch_bounds__(256) fix_ln(const float* __restrict__ ln_g,
                                              const float* __restrict__ ln_b)
{
    const int row = blockIdx.x;
    const int b = row / T_, t = row - b * T_;
    const int ch = t / CH;
    const int tx = threadIdx.x;

    float hv[4];
    float s = 0.f, s2 = 0.f;
    #pragma unroll
    for (int j = 0; j < 4; j++) {
        const int h = tx + j * 256;
        const float2 ph = *(const float2*)&g_pre[(size_t)row * NPRE + 2 * h];
        const float c = g_cP[(b * NC + ch) * H_ + h];
        const float v = fmaf(c, ph.x, ph.y);
        hv[j] = v;
        s += v;
        s2 = fmaf(v, v, s2);
    }

    __shared__ float rs[8], rs2[8];
    #pragma unroll
    for (int o = 16; o > 0; o >>= 1) {
        s  += __shfl_xor_sync(0xffffffffu, s,  o);
        s2 += __shfl_xor_sync(0xffffffffu, s2, o);
    }
    const int w = tx >> 5, l = tx & 31;
    if (l == 0) { rs[w] = s; rs2[w] = s2; }
    __syncthreads();
    if (w == 0) {
        s  = (l < 8) ? rs[l]  : 0.f;
        s2 = (l < 8) ? rs2[l] : 0.f;
        #pragma unroll
        for (int o = 4; o > 0; o >>= 1) {
            s  += __shfl_xor_sync(0xffffffffu, s,  o);
            s2 += __shfl_xor_sync(0xffffffffu, s2, o);
        }
        if (l == 0) { rs[0] = s; rs2[0] = s2; }
    }
    __syncthreads();
    const float mu  = rs[0] * (1.f / H_);
    const float var = rs2[0] * (1.f / H_) - mu * mu;
    const float rstd = rsqrtf(var + 1e-5f);

    #pragma unroll
    for (int j = 0; j < 4; j++) {
        const int h = tx + j * 256;
        g_hn[(size_t)row * H_ + h] =
            __float2half_rn(fmaf((hv[j] - mu) * rstd, ln_g[h], ln_b[h]));
    }
}

// ------------------------------- launch -------------------------------------------
extern "C" void kernel_launch(void* const* d_in, const int* in_sizes, int n_in,
                              void* d_out, int out_size)
{
    const float* x      = (const float*)d_in[0];
    const float* W_ih   = (const float*)d_in[1];
    const float* b_ih   = (const float*)d_in[2];
    const float* W_gate = (const float*)d_in[3];
    const float* b_gate = (const float*)d_in[4];
    const float* log_a  = (const float*)d_in[5];
    const float* ln_g   = (const float*)d_in[6];
    const float* ln_b   = (const float*)d_in[7];
    const float* W_out  = (const float*)d_in[8];
    const float* b_out  = (const float*)d_in[9];
    const float* W_proj = (const float*)d_in[10];
    const float* b_proj = (const float*)d_in[11];
    float* out = (float*)d_out;

    cudaFuncSetAttribute(gemm_f16, cudaFuncAttributeMaxDynamicSharedMemorySize, SMEM_BYTES);

    __half *p_xh, *p_hn, *p_WcatT, *p_WoutH, *p_WprojT, *p_WcT;
    float *p_pre, *p_Wc, *p_b2, *p_bc;
    cudaGetSymbolAddress((void**)&p_xh,     g_xh);
    cudaGetSymbolAddress((void**)&p_pre,    g_pre);
    cudaGetSymbolAddress((void**)&p_hn,     g_hn);
    cudaGetSymbolAddress((void**)&p_WcatT,  g_WcatT);
    cudaGetSymbolAddress((void**)&p_WoutH,  g_WoutH);
    cudaGetSymbolAddress((void**)&p_WprojT, g_WprojT);
    cudaGetSymbolAddress((void**)&p_Wc,     g_Wc);
    cudaGetSymbolAddress((void**)&p_WcT,    g_WcT);
    cudaGetSymbolAddress((void**)&p_b2,     g_b2);
    cudaGetSymbolAddress((void**)&p_bc,     g_bc);

    const dim3 blk(256);
    const dim3 tblk(32, 8);
    const dim3 tg(32, 32);

    // convert / transpose operands to fp16
    conv_h8<<<(int)((size_t)M_*D_/8/256), blk>>>((const float4*)x, (uint4*)p_xh);
    trans_h_il<<<tg, tblk>>>(W_ih,   p_WcatT, D_, H_, 0);   // row 2h
    trans_h_il<<<tg, tblk>>>(W_gate, p_WcatT, D_, H_, 1);   // row 2h+1
    trans_h<<<tg, tblk>>>(W_proj, p_WprojT, H_, D_);
    conv_h8<<<(int)((size_t)H_*H_/8/256), blk>>>((const float4*)W_out, (uint4*)p_WoutH);
    bias_concat<<<H_/256, blk>>>(b_ih, b_gate);
    bias_comb_part<<<dim3(D_/256, BCK), blk>>>(b_out, W_proj);
    bias_comb_final<<<D_/256, blk>>>(b_proj);

    // Wc = W_out @ W_proj (fp32), then transpose to fp16 [D][H]
    gemm_f16<<<dim3(D_/BN, H_/BM), blk, SMEM_BYTES>>>(p_WoutH, p_WprojT, nullptr, p_Wc,
                                                      H_, D_, 0, nullptr);
    trans_h<<<tg, tblk>>>(p_Wc, p_WcT, H_, D_);

    // fused [ih|gate] GEMM + in-epilogue chunk scan -> g_pre holds (P, h_local)
    gemm_f16<<<dim3(NPRE/BN, M_/BM), blk, SMEM_BYTES>>>(p_xh, p_WcatT, p_b2, p_pre,
                                                        D_, NPRE, 1, log_a);

    // carry scan + layernorm
    scan_pass2<<<(B_*H_)/256, blk>>>();
    fix_ln<<<M_, blk>>>(ln_g, ln_b);

    // out = hn @ Wc + bc
    gemm_f16<<<dim3(D_/BN, M_/BM), blk, SMEM_BYTES>>>(p_hn, p_WcT, p_bc, out,
                                                      H_, D_, 0, nullptr);
}